// round 15
// baseline (speedup 1.0000x reference)
#include <cuda_runtime.h>
#include <cstdint>

// VoxelHashTable: 2-level hash-grid trilinear interpolation.
// Inputs (metadata order):
//   d_in[0] query_pts (M,3) f32
//   d_in[1] feats0    (n0,32) f32
//   d_in[2] feats1    (n1,32) f32
//   d_in[3] h2v0      (2^20) i32
//   d_in[4] h2v1      (2^20) i32
// Output: (M, 64) f32  — [level0 32 | level1 32]
//
// CONVERGENT-LOAD layout. L1tex replays within-instruction wavefronts at
// ~2.07cyc vs ~1.0cyc across instructions; all previous shapes used divergent
// loads (32-way scattered hash LDG, 4-row gather LDG.128). Here every memory
// instruction touches at most 2 cache lines:
//   - half-warp = one query; lane&15 = float2 channel-pair of the 32-dim row
//   - feature row load: 16 lanes x LDG.64 = one 128B line per half
//     (2 lines per warp instruction)
//   - hash probes: BROADCAST — all 16 lanes of a half compute the same
//     corner address (base_hash + compile-time prime combo) and load it.
//     2 wavefronts/instruction, no shuffles, and the 8 probes per level are
//     independent -> issued back-to-back (deep MLP at the chain head).
// Weight math is lane-redundant but issue has 2.5x headroom (37% busy).
// Reciprocal-multiply instead of divide (validated R13: rel_err 6.6e-8).
// __launch_bounds__(256, 6): 40-reg budget for the 16 live probe results.

#define TSIZE_MASK ((1 << 20) - 1)

// PRIMES % 2^20 (exact):
#define PMX 455773
#define PMY 475301
#define PMZ 655287

#define INV_RES0 (1.0f / 0.12f)
#define INV_RES1 (1.0f / 0.24f)   // 0.24f == float32(0.12*2.0)

// Compile-time corner offset into the hash sum: corner bits (x,y,z)=(4,2,1).
#define COFF(c) (((c) & 4 ? PMX : 0) + ((c) & 2 ? PMY : 0) + ((c) & 1 ? PMZ : 0))

__global__ __launch_bounds__(256, 6) void voxel_hash_kernel(
    const float* __restrict__ q,
    const float* __restrict__ f0,
    const float* __restrict__ f1,
    const int* __restrict__ h0,
    const int* __restrict__ h1,
    float* __restrict__ out,
    int M)
{
    const int wid  = (blockIdx.x * blockDim.x + threadIdx.x) >> 5;
    const int lane = threadIdx.x & 31;

    const int half = lane >> 4;       // which query this half-warp owns
    const int c2   = lane & 15;       // float2 channel-pair (covers 8B of row)

    int qq = wid * 2 + half;
    const bool active = qq < M;
    if (qq >= M) qq = M - 1;          // clamp; store guarded below

    // Query point (lane-redundant within the half; 2 addresses per warp).
    const float qx = __ldg(q + qq * 3 + 0);
    const float qy = __ldg(q + qq * 3 + 1);
    const float qz = __ldg(q + qq * 3 + 2);

    // Both levels' scaled coords / fracs / hash bases (all lanes of the half).
    const float sx0 = qx * INV_RES0, sy0 = qy * INV_RES0, sz0 = qz * INV_RES0;
    const float bx0 = floorf(sx0), by0 = floorf(sy0), bz0 = floorf(sz0);
    const float fx0 = sx0 - bx0, fy0 = sy0 - by0, fz0 = sz0 - bz0;
    const int base0 = (int)bx0 * PMX + (int)by0 * PMY + (int)bz0 * PMZ;

    const float sx1 = qx * INV_RES1, sy1 = qy * INV_RES1, sz1 = qz * INV_RES1;
    const float bx1 = floorf(sx1), by1 = floorf(sy1), bz1 = floorf(sz1);
    const float fx1 = sx1 - bx1, fy1 = sy1 - by1, fz1 = sz1 - bz1;
    const int base1 = (int)bx1 * PMX + (int)by1 * PMY + (int)bz1 * PMZ;

    // ---- Level-0 probes: 8 independent broadcast loads (2 wf/instr) ----
    int v0[8];
    #pragma unroll
    for (int c = 0; c < 8; ++c) {
        const unsigned hv = ((unsigned)(base0 + COFF(c))) & TSIZE_MASK;
        v0[c] = __ldg(h0 + hv);
    }
    // ---- Level-1 probes ----
    int v1[8];
    #pragma unroll
    for (int c = 0; c < 8; ++c) {
        const unsigned hv = ((unsigned)(base1 + COFF(c))) & TSIZE_MASK;
        v1[c] = __ldg(h1 + hv);
    }

    const float* __restrict__ fp0 = f0 + c2 * 2;
    const float* __restrict__ fp1 = f1 + c2 * 2;

    // ---- Level-0 gather: 8 convergent LDG.64 row loads ----
    float2 acc0 = make_float2(0.f, 0.f);
    {
        const float gx = 1.0f - fx0, gy = 1.0f - fy0, gz = 1.0f - fz0;
        #pragma unroll
        for (int c = 0; c < 8; ++c) {
            // ((wx*wy)*wz) multiply order matches reference prod(axis=2).
            const float w = ((c & 4) ? fx0 : gx) *
                            ((c & 2) ? fy0 : gy) *
                            ((c & 1) ? fz0 : gz);
            const int v = v0[c];
            if (v >= 0) {
                const float2 f = __ldg((const float2*)(fp0 + (size_t)v * 32));
                acc0.x = fmaf(f.x, w, acc0.x);
                acc0.y = fmaf(f.y, w, acc0.y);
            }
        }
    }

    // ---- Level-1 gather ----
    float2 acc1 = make_float2(0.f, 0.f);
    {
        const float gx = 1.0f - fx1, gy = 1.0f - fy1, gz = 1.0f - fz1;
        #pragma unroll
        for (int c = 0; c < 8; ++c) {
            const float w = ((c & 4) ? fx1 : gx) *
                            ((c & 2) ? fy1 : gy) *
                            ((c & 1) ? fz1 : gz);
            const int v = v1[c];
            if (v >= 0) {
                const float2 f = __ldg((const float2*)(fp1 + (size_t)v * 32));
                acc1.x = fmaf(f.x, w, acc1.x);
                acc1.y = fmaf(f.y, w, acc1.y);
            }
        }
    }

    // Store: per query 2x 128B contiguous half-warp stores (2 wf each instr).
    if (active) {
        *(float2*)(out + (size_t)qq * 64 + c2 * 2)      = acc0;
        *(float2*)(out + (size_t)qq * 64 + 32 + c2 * 2) = acc1;
    }
}

extern "C" void kernel_launch(void* const* d_in, const int* in_sizes, int n_in,
                              void* d_out, int out_size)
{
    const float* q  = (const float*)d_in[0];
    const float* f0 = (const float*)d_in[1];
    const float* f1 = (const float*)d_in[2];
    const int*   h0 = (const int*)d_in[3];
    const int*   h1 = (const int*)d_in[4];
    float* out = (float*)d_out;

    const int M = in_sizes[0] / 3;
    const int warps = (M + 1) / 2;          // 2 queries per warp

    const int warps_per_block = 8;
    const int blocks = (warps + warps_per_block - 1) / warps_per_block;
    voxel_hash_kernel<<<blocks, warps_per_block * 32>>>(q, f0, f1, h0, h1, out, M);
}

// round 16
// speedup vs baseline: 1.1400x; 1.1400x over previous
#include <cuda_runtime.h>
#include <cstdint>

// VoxelHashTable: 2-level hash-grid trilinear interpolation.
// Inputs (metadata order):
//   d_in[0] query_pts (M,3) f32
//   d_in[1] feats0    (n0,32) f32
//   d_in[2] feats1    (n1,32) f32
//   d_in[3] h2v0      (2^20) i32
//   d_in[4] h2v1      (2^20) i32
// Output: (M, 64) f32  — [level0 32 | level1 32]
//
// Warp layout (1 warp = 2 queries — the R4 shape):
//   half  = lane>>4, level = (lane>>3)&1, s = lane&7 (float4 chunk)
//
// HASH PATH CHANGE vs R4: instead of one 32-lane scattered hash LDG + 8 SHFL
// broadcasts (within-instruction replays at ~2.07cyc/wf + full gather
// serialization behind the slowest lane), each lane issues 8 BROADCAST probe
// loads h[base + COFF(t)]: 4 distinct addresses per instruction (one per
// 8-lane group) -> 4 wavefronts at the ~1.0cyc/wf cross-instruction rate,
// zero shuffles, and 8 independent probe->feature chains with all probes in
// flight immediately. base is the same per-lane hash base R4 computed anyway;
// COFF(t) folds to a compile-time immediate (int wrap == mod 2^32, & mask ok).
// Unlike the R14 attempt: no redundant other-level math, gather stays LDG.128.
// Reciprocal-multiply instead of divide (validated: rel_err 6.6e-8).
// __launch_bounds__(256, 8): 32-reg budget, full-occupancy cap.

#define TSIZE_MASK ((1 << 20) - 1)

// PRIMES % 2^20 (exact):
#define PMX 455773
#define PMY 475301
#define PMZ 655287

#define INV_RES0 (1.0f / 0.12f)
#define INV_RES1 (1.0f / 0.24f)   // 0.24f == float32(0.12*2.0)

// Compile-time corner offset into the hash sum: corner bits (x,y,z)=(4,2,1).
#define COFF(c) (((c) & 4 ? PMX : 0) + ((c) & 2 ? PMY : 0) + ((c) & 1 ? PMZ : 0))

__global__ __launch_bounds__(256, 8) void voxel_hash_kernel(
    const float* __restrict__ q,
    const float* __restrict__ f0,
    const float* __restrict__ f1,
    const int* __restrict__ h0,
    const int* __restrict__ h1,
    float* __restrict__ out,
    int M)
{
    const int pair = (blockIdx.x * blockDim.x + threadIdx.x) >> 5;
    const int lane = threadIdx.x & 31;

    const int level = (lane >> 3) & 1;  // this lane's resolution level
    const int s     = lane & 7;         // float4 chunk within the 32-dim feature

    int qidx = pair * 2 + (lane >> 4);
    const bool active = qidx < M;
    if (qidx >= M) qidx = M - 1;        // clamp; store guarded below

    // Per-lane query point (2 distinct rows per warp).
    const float qx = __ldg(q + qidx * 3 + 0);
    const float qy = __ldg(q + qidx * 3 + 1);
    const float qz = __ldg(q + qidx * 3 + 2);

    // This lane's level only.
    const float inv_res = level ? INV_RES1 : INV_RES0;
    const float sx = qx * inv_res;
    const float sy = qy * inv_res;
    const float sz = qz * inv_res;

    const float bx = floorf(sx), by = floorf(sy), bz = floorf(sz);
    const float fx = sx - bx, fy = sy - by, fz = sz - bz;

    // Hash base for this (query, level); corner offsets are compile-time.
    const int hbase = (int)bx * PMX + (int)by * PMY + (int)bz * PMZ;
    const int* __restrict__ hp = level ? h1 : h0;

    // ---- 8 broadcast probes, all independent, issued back-to-back ----
    int v[8];
    #pragma unroll
    for (int t = 0; t < 8; ++t) {
        const unsigned hv = ((unsigned)(hbase + COFF(t))) & TSIZE_MASK;
        v[t] = __ldg(hp + hv);
    }

    const float gx = 1.0f - fx;
    const float gy = 1.0f - fy;
    const float gz = 1.0f - fz;
    const float* __restrict__ fp = (level ? f1 : f0) + s * 4;

    float4 acc = make_float4(0.f, 0.f, 0.f, 0.f);

    // ---- Gather: 8 independent probe->feature chains ----
    #pragma unroll
    for (int t = 0; t < 8; ++t) {
        // ((wx*wy)*wz) multiply order matches reference prod(axis=2).
        const float w = ((t & 4) ? fx : gx) *
                        ((t & 2) ? fy : gy) *
                        ((t & 1) ? fz : gz);
        const int vt = v[t];
        if (vt >= 0) {
            const float4 f = __ldg((const float4*)(fp + (size_t)vt * 32));
            acc.x = fmaf(f.x, w, acc.x);
            acc.y = fmaf(f.y, w, acc.y);
            acc.z = fmaf(f.z, w, acc.z);
            acc.w = fmaf(f.w, w, acc.w);
        }
    }

    // Each lane writes its own (query, level, chunk): 512B contiguous per warp.
    if (active) {
        *(float4*)(out + (size_t)qidx * 64 + level * 32 + s * 4) = acc;
    }
}

extern "C" void kernel_launch(void* const* d_in, const int* in_sizes, int n_in,
                              void* d_out, int out_size)
{
    const float* q  = (const float*)d_in[0];
    const float* f0 = (const float*)d_in[1];
    const float* f1 = (const float*)d_in[2];
    const int*   h0 = (const int*)d_in[3];
    const int*   h1 = (const int*)d_in[4];
    float* out = (float*)d_out;

    const int M = in_sizes[0] / 3;
    const int pairs = (M + 1) / 2;

    const int warps_per_block = 8;
    const int blocks = (pairs + warps_per_block - 1) / warps_per_block;
    voxel_hash_kernel<<<blocks, warps_per_block * 32>>>(q, f0, f1, h0, h1, out, M);
}